// round 11
// baseline (speedup 1.0000x reference)
#include <cuda_runtime.h>
#include <cuda_fp16.h>
#include <cstdint>

#define BATCH 32
#define TLEN  1024
#define HID   128
#define LD_H  144              // halves per padded smem row (288 B)
#define NT    256
#define LOG2E 1.4426950408889634f

#define SM_Q   0                       // 64 x 288 B = 18432
#define SM_K0  18432                   // 128 x 288 B = 36864
#define SM_K1  55296                   // 36864
#define SM_Y   92160                   // 2*128 floats = 1024
#define SM_TOT 93184                   // 2*256 floats = 2048
#define SMEM_BYTES 95232

__device__ __half g_xn[(size_t)BATCH * TLEN * HID];  // fp16, k-permuted per 16-group
__device__ float  g_nl2[BATCH * TLEN];               // -lambda * log2(e)

__device__ __forceinline__ float ex2f(float x) {
    float y; asm("ex2.approx.ftz.f32 %0, %1;" : "=f"(y) : "f"(x)); return y;
}
__device__ __forceinline__ void mma_f16(float* c, uint32_t a0, uint32_t a1,
                                        uint32_t a2, uint32_t a3,
                                        uint32_t b0, uint32_t b1) {
    asm volatile(
        "mma.sync.aligned.m16n8k16.row.col.f32.f16.f16.f32 "
        "{%0,%1,%2,%3}, {%4,%5,%6,%7}, {%8,%9}, {%0,%1,%2,%3};"
        : "+f"(c[0]), "+f"(c[1]), "+f"(c[2]), "+f"(c[3])
        : "r"(a0), "r"(a1), "r"(a2), "r"(a3), "r"(b0), "r"(b1));
}
__device__ __forceinline__ void cp16(uint32_t dst, const void* src) {
    asm volatile("cp.async.ca.shared.global [%0], [%1], 16;" :: "r"(dst), "l"(src));
}
__device__ __forceinline__ void cp_wait_all() {
    asm volatile("cp.async.wait_all;" ::: "memory");
}

// ---- Pass 1: normalize each token once; store fp16 k-permuted ----
__global__ __launch_bounds__(256)
void prep_kernel(const int* __restrict__ seq,
                 const float* __restrict__ embd,
                 const float* __restrict__ lam_w,
                 const float* __restrict__ lam_b)
{
    const int lane = threadIdx.x & 31;
    const int wid  = threadIdx.x >> 5;
    const int row  = blockIdx.x * 8 + wid;
    const unsigned FULL = 0xffffffffu;

    const int e = seq[row];
    const float* w = embd + (size_t)e * HID;
    float v[4] = { w[lane], w[lane+32], w[lane+64], w[lane+96] };
    float ss = v[0]*v[0] + v[1]*v[1] + v[2]*v[2] + v[3]*v[3];
    float dl = v[0]*lam_w[lane] + v[1]*lam_w[lane+32]
             + v[2]*lam_w[lane+64] + v[3]*lam_w[lane+96];
    #pragma unroll
    for (int off = 16; off; off >>= 1) {
        ss += __shfl_xor_sync(FULL, ss, off);
        dl += __shfl_xor_sync(FULL, dl, off);
    }
    const float inv = rsqrtf(ss);
    __half* dst = g_xn + (size_t)row * HID;
    #pragma unroll
    for (int q = 0; q < 4; ++q) {
        const int c = lane + 32 * q;
        const int gk = c >> 4, u = (c >> 1) & 7, par = c & 1;
        const int slot = (u < 4) ? 2 * u : 2 * (u - 4) + 1;   // half2-unit permute
        dst[gk * 16 + slot * 2 + par] = __float2half_rn(v[q] * inv);
    }
    if (lane == 0) g_nl2[row] = -__expf(dl + lam_b[0]) * LOG2E;
}

// ---- one 64x128 block: GEMM + fragment scan (single sync inside) ----
template<bool DIAG>
__device__ __forceinline__ void process_block(
    const __half* q_h, const __half* b_h, const float* yblk, float* totbuf,
    const float* nl2r, const int* rown, int qrow_off,
    float* carry, float* Sacc, float* Yacc,
    int mrow0, int cb, int cw, int g, int tg)
{
    const unsigned FULL = 0xffffffffu;

    float acc[2][4][4];
    #pragma unroll
    for (int mt = 0; mt < 2; mt++)
        #pragma unroll
        for (int nt = 0; nt < 4; nt++)
            #pragma unroll
            for (int j = 0; j < 4; j++) acc[mt][nt][j] = 0.f;

    #pragma unroll
    for (int ks = 0; ks < 8; ++ks) {
        const int boff = ks * 16 + 4 * tg;
        uint2 a[2][2];
        #pragma unroll
        for (int mt = 0; mt < 2; ++mt) {
            const int r = mrow0 + mt * 16 + g;
            a[mt][0] = *(const uint2*)&q_h[r * LD_H + boff];
            a[mt][1] = *(const uint2*)&q_h[(r + 8) * LD_H + boff];
        }
        #pragma unroll
        for (int nt = 0; nt < 4; ++nt) {
            const int n = cb + nt * 8 + g;
            uint2 b = *(const uint2*)&b_h[n * LD_H + boff];
            mma_f16(acc[0][nt], a[0][0].x, a[0][1].x, a[0][0].y, a[0][1].y, b.x, b.y);
            mma_f16(acc[1][nt], a[1][0].x, a[1][1].x, a[1][0].y, a[1][1].y, b.x, b.y);
        }
    }

    // mask + (x+1)/2
    const int col0 = cb + 2 * tg;
    #pragma unroll
    for (int i = 0; i < 4; ++i) {
        const int mt = i >> 1, c0i = (i & 1) * 2;
        const int rq = qrow_off + rown[i];
        #pragma unroll
        for (int nt = 0; nt < 4; nt++) {
            float va = fmaf(acc[mt][nt][c0i],     0.5f, 0.5f);
            float vb = fmaf(acc[mt][nt][c0i + 1], 0.5f, 0.5f);
            if (DIAG) {
                va = (col0 + nt * 8     < rq) ? va : 0.f;
                vb = (col0 + nt * 8 + 1 < rq) ? vb : 0.f;
            }
            acc[mt][nt][c0i]     = va;
            acc[mt][nt][c0i + 1] = vb;
        }
    }

    // per (row,frag): suffix over the 4 lanes of the group
    float sarr[4][4], ft[4][4];
    #pragma unroll
    for (int i = 0; i < 4; ++i) {
        const int mt = i >> 1, c0i = (i & 1) * 2;
        #pragma unroll
        for (int nt = 0; nt < 4; nt++) {
            float s = acc[mt][nt][c0i] + acc[mt][nt][c0i + 1];
            float u = __shfl_down_sync(FULL, s, 1);
            s += (tg < 3) ? u : 0.f;
            u = __shfl_down_sync(FULL, s, 2);
            s += (tg < 2) ? u : 0.f;
            sarr[i][nt] = s;
            ft[i][nt] = __shfl_sync(FULL, s, (threadIdx.x & 31) & ~3);
        }
    }

    if (tg == 0) {
        #pragma unroll
        for (int i = 0; i < 4; ++i)
            totbuf[cw * 64 + rown[i]] = ft[i][0] + ft[i][1] + ft[i][2] + ft[i][3];
    }
    cp_wait_all();          // next block's K/y copies complete (this thread's)
    __syncthreads();        // totals + smem copies visible, ONE barrier

    float2 yp[4];
    #pragma unroll
    for (int nt = 0; nt < 4; nt++)
        yp[nt] = *(const float2*)&yblk[cb + nt * 8 + 2 * tg];

    #pragma unroll
    for (int i = 0; i < 4; ++i) {
        const int r = rown[i];
        const float c0t = totbuf[r],       c1t = totbuf[64 + r],
                    c2t = totbuf[128 + r], c3t = totbuf[192 + r];
        float base = carry[i];
        if (cw == 0)      base += c1t + c2t + c3t;
        else if (cw == 1) base += c2t + c3t;
        else if (cw == 2) base += c3t;
        carry[i] += c0t + c1t + c2t + c3t;

        const int mt = i >> 1, c0i = (i & 1) * 2;
        float fsuf = 0.f;
        #pragma unroll
        for (int nt = 3; nt >= 0; --nt) {
            const float va = acc[mt][nt][c0i];
            const float vb = acc[mt][nt][c0i + 1];
            const float sa = base + fsuf + sarr[i][nt];
            const float wa = va * ex2f(nl2r[i] * sa);
            const float wb = vb * ex2f(nl2r[i] * (sa - va));
            Sacc[i] += wa + wb;
            Yacc[i] += yp[nt].x * wa + yp[nt].y * wb;
            fsuf += ft[i][nt];
        }
    }
}

// ---- Pass 2: main kernel, 64 query rows per CTA, 2 CTAs/SM, LPT ----
__global__ __launch_bounds__(NT, 2)
void ema_kernel(const float* __restrict__ y, float* __restrict__ out)
{
    extern __shared__ char smem[];
    __half* q_h  = (__half*)(smem + SM_Q);
    __half* k_h0 = (__half*)(smem + SM_K0);
    __half* k_h1 = (__half*)(smem + SM_K1);
    float*  y2   = (float*)(smem + SM_Y);
    float*  tot  = (float*)(smem + SM_TOT);

    const uint32_t q_sa = (uint32_t)__cvta_generic_to_shared(q_h);
    const uint32_t k_sa[2] = { (uint32_t)__cvta_generic_to_shared(k_h0),
                               (uint32_t)__cvta_generic_to_shared(k_h1) };
    const uint32_t y_sa = (uint32_t)__cvta_generic_to_shared(y2);

    const int tid  = threadIdx.x;
    const int lane = tid & 31;
    const int wid  = tid >> 5;
    const unsigned FULL = 0xffffffffu;

    const int g  = lane >> 2;
    const int tg = lane & 3;
    const int mrow0 = (wid >> 2) * 32;    // 2 (M) x 4 (N) warp grid
    const int cw    = wid & 3;
    const int cb    = cw * 32;

    // LPT: qi=7 CTAs first.  blockIdx = (7-qi)*64 + batch*2 + mhalf
    const int qi    = 7 - (blockIdx.x >> 6);
    const int batch = (blockIdx.x & 63) >> 1;
    const int mhalf = blockIdx.x & 1;
    const int t0    = qi * 128;
    const int qrow_off = mhalf * 64;

    const __half* xbase = g_xn + (size_t)batch * TLEN * HID;
    const float*  ybase = y + batch * TLEN;

    int rown[4];
    #pragma unroll
    for (int i = 0; i < 4; ++i) rown[i] = mrow0 + 8 * i + g;

    // prologue: Q (64 rows), K(qi) -> K0, y(qi)
    {
        const __half* qsrc = xbase + (size_t)(t0 + qrow_off) * HID;
        #pragma unroll
        for (int i = 0; i < 4; ++i) {                     // 1024 chunks
            const int c = tid + i * 256;
            const int r = c >> 4, j = c & 15;
            cp16(q_sa + r * 288 + j * 16, (const char*)qsrc + r * 256 + j * 16);
        }
        const __half* ksrc = xbase + (size_t)t0 * HID;
        #pragma unroll
        for (int i = 0; i < 8; ++i) {                     // 2048 chunks
            const int c = tid + i * 256;
            const int r = c >> 4, j = c & 15;
            cp16(k_sa[0] + r * 288 + j * 16, (const char*)ksrc + r * 256 + j * 16);
        }
        if (tid < 32) cp16(y_sa + tid * 16, ybase + qi * 128 + tid * 4);
    }
    float nl2r[4];
    #pragma unroll
    for (int i = 0; i < 4; ++i)
        nl2r[i] = g_nl2[batch * TLEN + t0 + qrow_off + rown[i]];
    cp_wait_all();
    __syncthreads();

    float carry[4] = {0.f, 0.f, 0.f, 0.f};
    float Sacc[4]  = {0.f, 0.f, 0.f, 0.f};
    float Yacc[4]  = {0.f, 0.f, 0.f, 0.f};

    for (int it = 0; it <= qi; ++it) {
        const int kb = qi - it;

        // prefetch K(kb-1) -> buffer ((it+1)&1), y(kb-1) -> y2[(it+1)&1]
        if (kb > 0) {
            const __half* ksrc = xbase + (size_t)(kb - 1) * 128 * HID;
            const uint32_t dst = k_sa[(it + 1) & 1];
            #pragma unroll
            for (int i = 0; i < 8; ++i) {
                const int c = tid + i * 256;
                const int r = c >> 4, j = c & 15;
                cp16(dst + r * 288 + j * 16, (const char*)ksrc + r * 256 + j * 16);
            }
            if (tid < 32)
                cp16(y_sa + ((it + 1) & 1) * 512 + tid * 16,
                     ybase + (kb - 1) * 128 + tid * 4);
        }

        float* totbuf = tot + (it & 1) * 256;
        const float* yblk = y2 + (it & 1) * 128;
        const __half* bsrc = (it & 1) ? k_h1 : k_h0;
        if (it == 0) {
            process_block<true>(q_h, bsrc, yblk, totbuf, nl2r, rown, qrow_off,
                                carry, Sacc, Yacc, mrow0, cb, cw, g, tg);
        } else {
            process_block<false>(q_h, bsrc, yblk, totbuf, nl2r, rown, qrow_off,
                                 carry, Sacc, Yacc, mrow0, cb, cw, g, tg);
        }
    }

    // ---- epilogue ----
    __syncthreads();   // weight loops done reading tot
    #pragma unroll
    for (int i = 0; i < 4; ++i) {
        float s = Sacc[i], yv = Yacc[i];
        s  += __shfl_xor_sync(FULL, s, 1);  s  += __shfl_xor_sync(FULL, s, 2);
        yv += __shfl_xor_sync(FULL, yv, 1); yv += __shfl_xor_sync(FULL, yv, 2);
        if (tg == 0) {
            tot[cw * 64 + rown[i]]       = s;
            tot[256 + cw * 64 + rown[i]] = yv;
        }
    }
    __syncthreads();
    if (cw == 0) {
        #pragma unroll
        for (int i = 0; i < 4; ++i) {
            const int r = rown[i];
            float S = tot[r] + tot[64 + r] + tot[128 + r] + tot[192 + r];
            float Y = tot[256 + r] + tot[320 + r] + tot[384 + r] + tot[448 + r];
            float o = Y / (S + 1e-6f);
            o = fminf(fmaxf(o, 0.01f), 0.99f);
            out[batch * TLEN + t0 + qrow_off + r] = o;
        }
    }
}

extern "C" void kernel_launch(void* const* d_in, const int* in_sizes, int n_in,
                              void* d_out, int out_size)
{
    const float* y    = (const float*)d_in[0];
    const int*   seq  = (const int*)  d_in[1];
    const float* embd = (const float*)d_in[2];
    const float* lw   = (const float*)d_in[3];
    const float* lb   = (const float*)d_in[4];
    float* out = (float*)d_out;

    cudaFuncSetAttribute(ema_kernel,
                         cudaFuncAttributeMaxDynamicSharedMemorySize, SMEM_BYTES);

    prep_kernel<<<BATCH * TLEN / 8, 256>>>(seq, embd, lw, lb);
    ema_kernel<<<BATCH * 8 * 2, NT, SMEM_BYTES>>>(y, out);
}

// round 12
// speedup vs baseline: 1.0459x; 1.0459x over previous
#include <cuda_runtime.h>
#include <cuda_fp16.h>
#include <cstdint>

#define BATCH 32
#define TLEN  1024
#define HID   128
#define LD_H  144              // halves per padded smem row (288 B)
#define NT    512
#define LOG2E 1.4426950408889634f

#define TILE_B (128 * LD_H * 2)        // 36864 B
#define SM_Q   0
#define SM_K0  TILE_B
#define SM_K1  (2 * TILE_B)
#define SM_Y   (3 * TILE_B)            // 2*128 floats
#define SM_TOT (SM_Y + 1024)           // 2*512 floats (double-buffered totals)
#define SMEM_BYTES (SM_TOT + 4096)

__device__ __half g_xn[(size_t)BATCH * TLEN * HID];  // fp16, k-permuted per 16-group
__device__ float  g_nl2[BATCH * TLEN];               // -lambda * log2(e)

__device__ __forceinline__ float ex2f(float x) {
    float y; asm("ex2.approx.ftz.f32 %0, %1;" : "=f"(y) : "f"(x)); return y;
}
__device__ __forceinline__ void mma_f16(float* c, uint32_t a0, uint32_t a1,
                                        uint32_t a2, uint32_t a3,
                                        uint32_t b0, uint32_t b1) {
    asm volatile(
        "mma.sync.aligned.m16n8k16.row.col.f32.f16.f16.f32 "
        "{%0,%1,%2,%3}, {%4,%5,%6,%7}, {%8,%9}, {%0,%1,%2,%3};"
        : "+f"(c[0]), "+f"(c[1]), "+f"(c[2]), "+f"(c[3])
        : "r"(a0), "r"(a1), "r"(a2), "r"(a3), "r"(b0), "r"(b1));
}
__device__ __forceinline__ void cp16(uint32_t dst, const void* src) {
    asm volatile("cp.async.ca.shared.global [%0], [%1], 16;" :: "r"(dst), "l"(src));
}
__device__ __forceinline__ void cp_wait_all() {
    asm volatile("cp.async.wait_all;" ::: "memory");
}

// ---- Pass 1: normalize each token once; store fp16 k-permuted ----
__global__ __launch_bounds__(256)
void prep_kernel(const int* __restrict__ seq,
                 const float* __restrict__ embd,
                 const float* __restrict__ lam_w,
                 const float* __restrict__ lam_b)
{
    const int lane = threadIdx.x & 31;
    const int wid  = threadIdx.x >> 5;
    const int row  = blockIdx.x * 8 + wid;
    const unsigned FULL = 0xffffffffu;

    const int e = seq[row];
    const float* w = embd + (size_t)e * HID;
    float v[4] = { w[lane], w[lane+32], w[lane+64], w[lane+96] };
    float ss = v[0]*v[0] + v[1]*v[1] + v[2]*v[2] + v[3]*v[3];
    float dl = v[0]*lam_w[lane] + v[1]*lam_w[lane+32]
             + v[2]*lam_w[lane+64] + v[3]*lam_w[lane+96];
    #pragma unroll
    for (int off = 16; off; off >>= 1) {
        ss += __shfl_xor_sync(FULL, ss, off);
        dl += __shfl_xor_sync(FULL, dl, off);
    }
    const float inv = rsqrtf(ss);
    __half* dst = g_xn + (size_t)row * HID;
    #pragma unroll
    for (int q = 0; q < 4; ++q) {
        const int c = lane + 32 * q;
        const int gk = c >> 4, u = (c >> 1) & 7, par = c & 1;
        const int slot = (u < 4) ? 2 * u : 2 * (u - 4) + 1;   // half2-unit permute
        dst[gk * 16 + slot * 2 + par] = __float2half_rn(v[q] * inv);
    }
    if (lane == 0) g_nl2[row] = -__expf(dl + lam_b[0]) * LOG2E;
}

// ---- one 128x128 key block: GEMM + fragment scan (single sync inside) ----
template<bool DIAG>
__device__ __forceinline__ void process_block(
    const __half* q_h, const __half* b_h, const float* yblk, float* totbuf,
    const float* nl2r, const int* rown, float* carry, float* Sacc, float* Yacc,
    int mrow0, int cb, int cw, int g, int tg)
{
    const unsigned FULL = 0xffffffffu;
    // diag: fragments with cb > mrow0 are entirely above the strict-lower
    // triangle -> masked to zero anyway; skip their GEMM.
    const bool live = !DIAG || (cb <= mrow0);

    float acc[2][4][4];
    #pragma unroll
    for (int mt = 0; mt < 2; mt++)
        #pragma unroll
        for (int nt = 0; nt < 4; nt++)
            #pragma unroll
            for (int j = 0; j < 4; j++) acc[mt][nt][j] = 0.f;

    if (live) {
        #pragma unroll
        for (int ks = 0; ks < 8; ++ks) {
            const int boff = ks * 16 + 4 * tg;
            uint2 a[2][2];
            #pragma unroll
            for (int mt = 0; mt < 2; ++mt) {
                const int r = mrow0 + mt * 16 + g;
                a[mt][0] = *(const uint2*)&q_h[r * LD_H + boff];
                a[mt][1] = *(const uint2*)&q_h[(r + 8) * LD_H + boff];
            }
            #pragma unroll
            for (int nt = 0; nt < 4; ++nt) {
                const int n = cb + nt * 8 + g;
                uint2 b = *(const uint2*)&b_h[n * LD_H + boff];
                mma_f16(acc[0][nt], a[0][0].x, a[0][1].x, a[0][0].y, a[0][1].y, b.x, b.y);
                mma_f16(acc[1][nt], a[1][0].x, a[1][1].x, a[1][0].y, a[1][1].y, b.x, b.y);
            }
        }
    }

    // mask + (x+1)/2
    const int col0 = cb + 2 * tg;
    #pragma unroll
    for (int i = 0; i < 4; ++i) {
        const int mt = i >> 1, c0i = (i & 1) * 2;
        #pragma unroll
        for (int nt = 0; nt < 4; nt++) {
            float va = fmaf(acc[mt][nt][c0i],     0.5f, 0.5f);
            float vb = fmaf(acc[mt][nt][c0i + 1], 0.5f, 0.5f);
            if (DIAG) {
                va = (col0 + nt * 8     < rown[i]) ? va : 0.f;
                vb = (col0 + nt * 8 + 1 < rown[i]) ? vb : 0.f;
            }
            acc[mt][nt][c0i]     = va;
            acc[mt][nt][c0i + 1] = vb;
        }
    }

    // per (row,frag): suffix over the 4 lanes of the group
    float sarr[4][4], ft[4][4];
    #pragma unroll
    for (int i = 0; i < 4; ++i) {
        const int mt = i >> 1, c0i = (i & 1) * 2;
        #pragma unroll
        for (int nt = 0; nt < 4; nt++) {
            float s = acc[mt][nt][c0i] + acc[mt][nt][c0i + 1];
            float u = __shfl_down_sync(FULL, s, 1);
            s += (tg < 3) ? u : 0.f;
            u = __shfl_down_sync(FULL, s, 2);
            s += (tg < 2) ? u : 0.f;
            sarr[i][nt] = s;
            ft[i][nt] = __shfl_sync(FULL, s, (threadIdx.x & 31) & ~3);
        }
    }

    if (tg == 0) {
        #pragma unroll
        for (int i = 0; i < 4; ++i)
            totbuf[cw * 128 + rown[i]] = ft[i][0] + ft[i][1] + ft[i][2] + ft[i][3];
    }
    cp_wait_all();          // prefetched K/y for next block complete (this thread)
    __syncthreads();        // totals visible + smem copies visible, ONE barrier

    float2 yp[4];
    #pragma unroll
    for (int nt = 0; nt < 4; nt++)
        yp[nt] = *(const float2*)&yblk[cb + nt * 8 + 2 * tg];

    #pragma unroll
    for (int i = 0; i < 4; ++i) {
        const int r = rown[i];
        const float c0t = totbuf[r],       c1t = totbuf[128 + r],
                    c2t = totbuf[256 + r], c3t = totbuf[384 + r];
        float base = carry[i];
        if (cw == 0)      base += c1t + c2t + c3t;
        else if (cw == 1) base += c2t + c3t;
        else if (cw == 2) base += c3t;
        carry[i] += c0t + c1t + c2t + c3t;   // register carry, every lane

        if (live) {
            const int mt = i >> 1, c0i = (i & 1) * 2;
            float fsuf = 0.f;
            #pragma unroll
            for (int nt = 3; nt >= 0; --nt) {
                const float va = acc[mt][nt][c0i];
                const float vb = acc[mt][nt][c0i + 1];
                const float sa = base + fsuf + sarr[i][nt];
                const float wa = va * ex2f(nl2r[i] * sa);
                const float wb = vb * ex2f(nl2r[i] * (sa - va));
                Sacc[i] += wa + wb;
                Yacc[i] += yp[nt].x * wa + yp[nt].y * wb;
                fsuf += ft[i][nt];
            }
        }
    }
}

// ---- Pass 2: main kernel, exact 8-unit bins, single wave of 144 CTAs ----
__global__ __launch_bounds__(NT, 1)
void ema_kernel(const float* __restrict__ y, float* __restrict__ out)
{
    extern __shared__ char smem[];
    __half* q_h  = (__half*)(smem + SM_Q);
    __half* k_h0 = (__half*)(smem + SM_K0);
    __half* k_h1 = (__half*)(smem + SM_K1);
    float*  y2   = (float*)(smem + SM_Y);
    float*  tot  = (float*)(smem + SM_TOT);

    const uint32_t q_sa = (uint32_t)__cvta_generic_to_shared(q_h);
    const uint32_t k_sa[2] = { (uint32_t)__cvta_generic_to_shared(k_h0),
                               (uint32_t)__cvta_generic_to_shared(k_h1) };
    const uint32_t y_sa = (uint32_t)__cvta_generic_to_shared(y2);

    const int tid  = threadIdx.x;
    const int lane = tid & 31;
    const int wid  = tid >> 5;
    const unsigned FULL = 0xffffffffu;

    const int g  = lane >> 2;
    const int tg = lane & 3;
    const int mrow0 = (wid >> 2) * 32;
    const int cw    = wid & 3;
    const int cb    = cw * 32;

    // job table: every CTA gets exactly 8 work units
    const int bid = blockIdx.x;
    int jb[2], jq[2], njobs;
    if (bid < 32)       { jb[0] = bid;            jq[0] = 7; njobs = 1; }
    else if (bid < 64)  { jb[0] = bid - 32;  jq[0] = 6; jb[1] = jb[0]; jq[1] = 0; njobs = 2; }
    else if (bid < 96)  { jb[0] = bid - 64;  jq[0] = 5; jb[1] = jb[0]; jq[1] = 1; njobs = 2; }
    else if (bid < 128) { jb[0] = bid - 96;  jq[0] = 4; jb[1] = jb[0]; jq[1] = 2; njobs = 2; }
    else { jb[0] = 2 * (bid - 128); jq[0] = 3; jb[1] = jb[0] + 1; jq[1] = 3; njobs = 2; }

    int rown[4];
    #pragma unroll
    for (int i = 0; i < 4; ++i) rown[i] = mrow0 + 8 * i + g;

    for (int j = 0; j < njobs; ++j) {
        const int batch = jb[j];
        const int qi    = jq[j];
        const int t0    = qi * 128;

        const __half* xbase = g_xn + (size_t)batch * TLEN * HID;
        const float*  ybase = y + batch * TLEN;

        __syncthreads();    // previous job fully done with smem

        // prologue: Q tile + y(qi)
        {
            const __half* qsrc = xbase + (size_t)t0 * HID;
            #pragma unroll
            for (int i = 0; i < 4; ++i) {
                const int c = tid + i * 512;
                const int r = c >> 4, jj = c & 15;
                cp16(q_sa + r * 288 + jj * 16, (const char*)qsrc + r * 256 + jj * 16);
            }
            if (tid < 32) cp16(y_sa + tid * 16, ybase + qi * 128 + tid * 4);
        }
        float nl2r[4];
        #pragma unroll
        for (int i = 0; i < 4; ++i)
            nl2r[i] = g_nl2[batch * TLEN + t0 + rown[i]];
        cp_wait_all();
        __syncthreads();

        float carry[4] = {0.f, 0.f, 0.f, 0.f};
        float Sacc[4]  = {0.f, 0.f, 0.f, 0.f};
        float Yacc[4]  = {0.f, 0.f, 0.f, 0.f};

        for (int it = 0; it <= qi; ++it) {
            const int kb = qi - it;

            // prefetch K(kb-1) -> kbuf[it&1], y(kb-1) -> ybuf[(it+1)&1]
            if (kb > 0) {
                const __half* ksrc = xbase + (size_t)(kb - 1) * 128 * HID;
                const uint32_t dst = k_sa[it & 1];
                #pragma unroll
                for (int i = 0; i < 4; ++i) {
                    const int c = tid + i * 512;
                    const int r = c >> 4, jj = c & 15;
                    cp16(dst + r * 288 + jj * 16, (const char*)ksrc + r * 256 + jj * 16);
                }
                if (tid < 32)
                    cp16(y_sa + ((it + 1) & 1) * 512 + tid * 16,
                         ybase + (kb - 1) * 128 + tid * 4);
            }

            float* totbuf = tot + (it & 1) * 512;
            const float* yblk = y2 + (it & 1) * 128;
            if (it == 0) {
                process_block<true>(q_h, q_h, yblk, totbuf, nl2r, rown,
                                    carry, Sacc, Yacc, mrow0, cb, cw, g, tg);
            } else {
                const __half* bsrc = (it & 1) ? k_h0 : k_h1;   // written at it-1
                process_block<false>(q_h, bsrc, yblk, totbuf, nl2r, rown,
                                     carry, Sacc, Yacc, mrow0, cb, cw, g, tg);
            }
        }

        // ---- epilogue ----
        __syncthreads();   // weight loops done reading tot
        #pragma unroll
        for (int i = 0; i < 4; ++i) {
            float s = Sacc[i], yv = Yacc[i];
            s  += __shfl_xor_sync(FULL, s, 1);  s  += __shfl_xor_sync(FULL, s, 2);
            yv += __shfl_xor_sync(FULL, yv, 1); yv += __shfl_xor_sync(FULL, yv, 2);
            if (tg == 0) {
                tot[cw * 128 + rown[i]]       = s;
                tot[512 + cw * 128 + rown[i]] = yv;
            }
        }
        __syncthreads();
        if (cw == 0) {
            #pragma unroll
            for (int i = 0; i < 4; ++i) {
                const int r = rown[i];
                float S = tot[r] + tot[128 + r] + tot[256 + r] + tot[384 + r];
                float Y = tot[512 + r] + tot[640 + r] + tot[768 + r] + tot[896 + r];
                float o = Y / (S + 1e-6f);
                o = fminf(fmaxf(o, 0.01f), 0.99f);
                out[batch * TLEN + t0 + r] = o;
            }
        }
    }
}

extern "C" void kernel_launch(void* const* d_in, const int* in_sizes, int n_in,
                              void* d_out, int out_size)
{
    const float* y    = (const float*)d_in[0];
    const int*   seq  = (const int*)  d_in[1];
    const float* embd = (const float*)d_in[2];
    const float* lw   = (const float*)d_in[3];
    const float* lb   = (const float*)d_in[4];
    float* out = (float*)d_out;

    cudaFuncSetAttribute(ema_kernel,
                         cudaFuncAttributeMaxDynamicSharedMemorySize, SMEM_BYTES);

    prep_kernel<<<BATCH * TLEN / 8, 256>>>(seq, embd, lw, lb);
    ema_kernel<<<144, NT, SMEM_BYTES>>>(y, out);
}